// round 9
// baseline (speedup 1.0000x reference)
#include <cuda_runtime.h>
#include <cuda_bf16.h>
#include <math.h>

#define CC        16
#define KK        5
#define LL        131072
#define L_OUT     65536

#define THREADS   256
// Per warp: 4 quads/lane * 32 lanes * 4 floats = 512 inputs -> 256 outputs.
// Per block (8 warps): 4096 inputs -> 2048 outputs.
#define WARP_IN   512
#define BLOCK_OUT 2048

__device__ __forceinline__ float tanh_approx(float x) {
    float r;
    asm("tanh.approx.f32 %0, %1;" : "=f"(r) : "f"(x));
    return r;
}
__device__ __forceinline__ float ex2_approx(float x) {
    float r;
    asm("ex2.approx.f32 %0, %1;" : "=f"(r) : "f"(x));
    return r;
}
__device__ __forceinline__ float lg2_approx(float x) {
    float r;
    asm("lg2.approx.f32 %0, %1;" : "=f"(r) : "f"(x));
    return r;
}

// f(x) = lg2(1 + ex2(-x*log2e)); logsigmoid(x) = -ln2 * f(x) (folded into weights).
__device__ __forceinline__ float ls_core(float x) {
    const float LOG2E = 1.4426950408889634f;
    float e = ex2_approx(-x * LOG2E);
    return lg2_approx(1.0f + e);
}

__global__ __launch_bounds__(THREADS)
void Model_41266045780566_kernel(const float* __restrict__ x,
                                 const float* __restrict__ w,     // [C, K]
                                 const float* __restrict__ bias,  // [C]
                                 float* __restrict__ out) {
    const int tid  = threadIdx.x;
    const int lane = tid & 31;
    const int wid  = tid >> 5;
    const int row  = blockIdx.y;                 // b*C + c
    const int c    = row & (CC - 1);
    const long long row_in  = (long long)row * LL;
    const long long row_out = (long long)row * L_OUT;

    // Warp input base within the row (floats); multiple of 512.
    const int Wl = blockIdx.x * (BLOCK_OUT * 2) + wid * WARP_IN;
    const float* xp = x + row_in + Wl;

    // ---- Coalesced loads: quad k of this lane = floats [Wl + 128k + 4*lane, +4) ----
    const float4* xv = (const float4*)xp;
    float4 v0 = __ldcs(xv + lane);
    float4 v1 = __ldcs(xv + 32 + lane);
    float4 v2 = __ldcs(xv + 64 + lane);
    float4 v3 = __ldcs(xv + 96 + lane);

    float qx[4], qy[4], qz[4], qw[4];
    qx[0] = ls_core(v0.x); qy[0] = ls_core(v0.y); qz[0] = ls_core(v0.z); qw[0] = ls_core(v0.w);
    qx[1] = ls_core(v1.x); qy[1] = ls_core(v1.y); qz[1] = ls_core(v1.z); qw[1] = ls_core(v1.w);
    qx[2] = ls_core(v2.x); qy[2] = ls_core(v2.y); qz[2] = ls_core(v2.z); qw[2] = ls_core(v2.w);
    qx[3] = ls_core(v3.x); qy[3] = ls_core(v3.y); qz[3] = ls_core(v3.z); qw[3] = ls_core(v3.w);

    // Weights pre-scaled by -ln2; bias folded into the shuffled partials.
    const float LN2 = 0.6931471805599453f;
    const float w0 = -LN2 * __ldg(&w[c * KK + 0]);
    const float w1 = -LN2 * __ldg(&w[c * KK + 1]);
    const float w2 = -LN2 * __ldg(&w[c * KK + 2]);
    const float w3 = -LN2 * __ldg(&w[c * KK + 3]);
    const float w4 = -LN2 * __ldg(&w[c * KK + 4]);
    const float bc = __ldg(&bias[c]);

    // Quad k, lane l: base B = Wl + 128k + 4l.
    // Output o0 = B/2   window f(B-2..B+2): needs prev lane's  t = w0*qz + w1*qw + bc
    // Output o1 = B/2+1 window f(B..B+4)  : needs next lane's  h = w4*qx + bc
    float t[4], h[4];
    #pragma unroll
    for (int k = 0; k < 4; ++k) {
        t[k] = fmaf(qz[k], w0, fmaf(qw[k], w1, bc));
        h[k] = fmaf(qx[k], w4, bc);
    }

    const unsigned F = 0xffffffffu;
    float ts[4], hs[4];
    #pragma unroll
    for (int k = 0; k < 4; ++k) {
        ts[k] = __shfl_up_sync(F, t[k], 1);      // from lane-1, same quad
        hs[k] = __shfl_down_sync(F, h[k], 1);    // from lane+1, same quad
    }
    // Boundary broadcasts: lane 0 quad k (k>=1) takes lane31 quad k-1's t;
    // lane 31 quad k (k<=2) takes lane0 quad k+1's h.
    float bt0 = __shfl_sync(F, t[0], 31);
    float bt1 = __shfl_sync(F, t[1], 31);
    float bt2 = __shfl_sync(F, t[2], 31);
    float bh1 = __shfl_sync(F, h[1], 0);
    float bh2 = __shfl_sync(F, h[2], 0);
    float bh3 = __shfl_sync(F, h[3], 0);

    if (lane == 0) {
        ts[1] = bt0; ts[2] = bt1; ts[3] = bt2;
        // quad 0: needs f(Wl-2), f(Wl-1) from global (clamped -> edge replication)
        int gm2 = max(Wl - 2, 0);
        int gm1 = max(Wl - 1, 0);
        float f2 = ls_core(__ldg(&x[row_in + gm2]));
        float f1 = ls_core(__ldg(&x[row_in + gm1]));
        ts[0] = fmaf(f2, w0, fmaf(f1, w1, bc));
    }
    if (lane == 31) {
        hs[0] = bh1; hs[1] = bh2; hs[2] = bh3;
        // quad 3: needs f(Wl+512) from global (clamped)
        int gp = min(Wl + WARP_IN, LL - 1);
        float fp = ls_core(__ldg(&x[row_in + gp]));
        hs[3] = fmaf(fp, w4, bc);
    }

    // ---- Compute + coalesced stores ----
    // o0 = Wl/2 + 64k + 2*lane  (even -> aligned float2 store)
    float2* ov = (float2*)(out + row_out + (Wl >> 1));
    #pragma unroll
    for (int k = 0; k < 4; ++k) {
        float a0 = fmaf(qz[k], w4, fmaf(qy[k], w3, fmaf(qx[k], w2, ts[k])));
        float a1 = fmaf(qw[k], w3, fmaf(qz[k], w2, fmaf(qy[k], w1, fmaf(qx[k], w0, hs[k]))));
        __stcs(ov + 32 * k + lane, make_float2(tanh_approx(a0), tanh_approx(a1)));
    }
}

extern "C" void kernel_launch(void* const* d_in, const int* in_sizes, int n_in,
                              void* d_out, int out_size) {
    const float* x    = (const float*)d_in[0];
    const float* w    = (const float*)d_in[1];
    const float* bias = (const float*)d_in[2];
    float* out = (float*)d_out;

    const int rows = in_sizes[0] / LL;               // B * C = 512
    dim3 grid(L_OUT / BLOCK_OUT, rows);              // 32 x 512
    Model_41266045780566_kernel<<<grid, THREADS>>>(x, w, bias, out);
}